// round 15
// baseline (speedup 1.0000x reference)
#include <cuda_runtime.h>
#include <cuda_fp16.h>
#include <cstdint>
#include <math.h>

#define Bv 8
#define Sv 1024
#define Dv 512
#define Hv 256
#define Nv 64
#define SDv 128
#define NHv 4
#define DHv 64

#define CLW 8   // cluster width (ranks per batch)

// ---- device scratch (no allocations allowed) ----
__device__ float g_qwx[(size_t)Bv * Sv * 512];   // per token: [q(128) | wr(128) | xh0(256)]
__device__ float g_ba[(size_t)Bv * Sv * 64];     // precomputed attn2 softmax
__device__ float g_rx[(size_t)Bv * Sv * 384];    // per token: [read(128) | xh_final(256)]
__device__ __align__(256) __half g_h[591872];    // fp16 weight pack

#define H_QKV   0          // 2*256*768 = 393216
#define H_WO    393216     // 2*256*256 = 131072
#define H_BPW   524288     // 128*256   = 32768
#define H_SUPW  557056     // 256*128   = 32768
#define H_WBETA 589824     // 2*256*4   = 2048
#define H_TOTAL 591872

// smem float-index layout for k_rec
#define SM_SLOTS 0        // 8192
#define SM_PART  8192     // 3072
#define SM_QN    11264    // 128  (next-token q for fused logits)
#define SM_WR    11392    // 128
#define SM_XH    11520    // 256
#define SM_ABUF  11776    // 64
#define SM_A     11840    // 64
#define SM_BA    11904    // 64
#define SM_G2    11968    // 64
#define SM_CB    12032    // 64
#define SM_C1    12096    // 64
#define SM_C2    12160    // 64
#define SM_T1    12224    // 64
#define SM_BIND  12288    // 128
#define SM_QKV   12416    // 1536 = 2 sets x 768
#define SM_BETA  14208    // 4
#define SM_O     14212    // 256
#define SM_U     14468    // 256 = 2 x 128
#define SM_EXCH  14724    // 512 = 2 x 256
#define SM_WOUT  15236    // 512 = 2 x 256
#define SM_MV    15748    // 4
#define SM_BQKV2 15752    // 192
#define SM_BO2   15944    // 64
#define SM_LNG   16008    // 512
#define SM_LNB   16520    // 512
#define SM_BPB2  17032    // 32
#define SM_SUPB  17064    // 128
#define SM_BBETA 17192    // 8
#define SM_MBAR  17200    // 24 floats = 12 u64 mbarriers
#define SM_HBASE 17224    // halves start (16B aligned)
// half offsets (relative to half base)
#define WS_QKV  0         // 2*256*96 = 49152
#define WS_WO   49152     // 2*256*32 = 16384
#define WS_BP   65536     // 128*32   = 4096
#define WS_SUP  69632     // 256*16   = 4096
#define WS_BETA 73728     // 2*256*4  = 2048
#define SMEM_REC_BYTES (SM_HBASE * 4 + 75776 * 2)   // 220448

// ---- cluster / mbarrier helpers ----
__device__ __forceinline__ void cluster_sync_() {
    asm volatile("barrier.cluster.arrive.aligned;" ::: "memory");
    asm volatile("barrier.cluster.wait.aligned;" ::: "memory");
}
__device__ __forceinline__ void mbar_init(float* lmbar, unsigned cnt) {
    unsigned m = (unsigned)__cvta_generic_to_shared(lmbar);
    asm volatile("mbarrier.init.shared.b64 [%0], %1;" :: "r"(m), "r"(cnt) : "memory");
}
__device__ __forceinline__ void mbar_expect(float* lmbar, unsigned tx) {
    unsigned m = (unsigned)__cvta_generic_to_shared(lmbar);
    asm volatile("mbarrier.arrive.expect_tx.shared.b64 _, [%0], %1;" :: "r"(m), "r"(tx) : "memory");
}
// bounded-spin wait: never hangs the container
__device__ __forceinline__ void mbar_wait(float* lmbar, unsigned parity) {
    unsigned m = (unsigned)__cvta_generic_to_shared(lmbar);
    unsigned done = 0;
    long long t0 = clock64();
    while (!done) {
        asm volatile("{\n\t.reg .pred P;\n\t"
            "mbarrier.try_wait.parity.acquire.cluster.shared::cta.b64 P, [%1], %2, 0x989680;\n\t"
            "selp.b32 %0, 1, 0, P;\n\t}"
            : "=r"(done) : "r"(m), "r"(parity) : "memory");
        if (!done && (clock64() - t0) > 200000000LL) break;   // ~0.1 s watchdog
    }
}
__device__ __forceinline__ void st_async_f32(float* lptr, float* lmbar, int rr, float v) {
    unsigned a = (unsigned)__cvta_generic_to_shared(lptr);
    unsigned m = (unsigned)__cvta_generic_to_shared(lmbar);
    unsigned ra, rm;
    asm volatile("mapa.shared::cluster.u32 %0, %1, %2;" : "=r"(ra) : "r"(a), "r"(rr));
    asm volatile("mapa.shared::cluster.u32 %0, %1, %2;" : "=r"(rm) : "r"(m), "r"(rr));
    asm volatile("st.async.shared::cluster.mbarrier::complete_tx::bytes.b32 [%0], %1, [%2];"
                 :: "r"(ra), "r"(__float_as_uint(v)), "r"(rm) : "memory");
}
__device__ __forceinline__ void bcast_async(float* lptr, float* lmbar, float v) {
#pragma unroll
    for (int rr = 0; rr < CLW; rr++) st_async_f32(lptr, lmbar, rr, v);
}

// fp16 vec8 FMA helper
#define FMA8(w, xv) do { \
    half2 h0 = *(half2*)&(w).x, h1 = *(half2*)&(w).y, h2 = *(half2*)&(w).z, h3 = *(half2*)&(w).w; \
    a0 += (xv) * __low2float(h0); a1 += (xv) * __high2float(h0); \
    a2 += (xv) * __low2float(h1); a3 += (xv) * __high2float(h1); \
    a4 += (xv) * __low2float(h2); a5 += (xv) * __high2float(h2); \
    a6 += (xv) * __low2float(h3); a7 += (xv) * __high2float(h3); } while (0)

// ---------------------------------------------------------------------------
__global__ __launch_bounds__(512) void k_cvt(
    const float* __restrict__ wqkv, const float* __restrict__ wo,
    const float* __restrict__ bpw, const float* __restrict__ supw,
    const float* __restrict__ wbeta)
{
    int i = blockIdx.x * 512 + threadIdx.x;
    if (i >= H_TOTAL) return;
    float v;
    if (i < H_WO)        v = wqkv[i];
    else if (i < H_BPW)  v = wo[i - H_WO];
    else if (i < H_SUPW) v = bpw[i - H_BPW];
    else if (i < H_WBETA) v = supw[i - H_SUPW];
    else                 v = wbeta[i - H_WBETA];
    g_h[i] = __float2half(v);
}

// ---------------------------------------------------------------------------
__global__ __launch_bounds__(512) void k_pre(
    const float* __restrict__ x,
    const float* __restrict__ sb_wq, const float* __restrict__ sb_bq,
    const float* __restrict__ sb_ww, const float* __restrict__ sb_bw,
    const float* __restrict__ p_win, const float* __restrict__ p_bin)
{
    __shared__ float xs[16 * 512];
    const int t0 = blockIdx.x * 16;
    const int tid = threadIdx.x;
    const float* xb = x + (size_t)t0 * 512;
    for (int idx = tid; idx < 16 * 512; idx += 512) xs[idx] = xb[idx];
    __syncthreads();

    const int c = tid;
    const float* W; int ld; float bias;
    if (c < 128)      { W = sb_wq + c;         ld = 128; bias = sb_bq[c]; }
    else if (c < 256) { W = sb_ww + (c - 128); ld = 128; bias = sb_bw[c - 128]; }
    else              { W = p_win + (c - 256); ld = 256; bias = p_bin[c - 256]; }

    float acc[16];
#pragma unroll
    for (int t = 0; t < 16; t++) acc[t] = 0.f;
    for (int i = 0; i < 512; i++) {
        float w = W[(size_t)i * ld];
#pragma unroll
        for (int t = 0; t < 16; t++) acc[t] += xs[t * 512 + i] * w;
    }
#pragma unroll
    for (int t = 0; t < 16; t++)
        g_qwx[((size_t)(t0 + t)) * 512 + c] = acc[t] + bias;
}

// ---------------------------------------------------------------------------
__global__ __launch_bounds__(256) void k_ba(
    const float* __restrict__ b_wq, const float* __restrict__ b_bq,
    const float* __restrict__ b_keys)
{
    __shared__ float s_x[8 * 256];
    __shared__ float s_keys[64 * 129];
    __shared__ float s_bq[8 * 128];
    const int t0 = blockIdx.x * 8;
    const int tid = threadIdx.x;

    for (int idx = tid; idx < 8 * 256; idx += 256) {
        int t = idx >> 8, i = idx & 255;
        s_x[idx] = g_qwx[((size_t)(t0 + t)) * 512 + 256 + i];
    }
    for (int idx = tid; idx < 64 * 128; idx += 256) {
        int n = idx >> 7, k = idx & 127;
        s_keys[n * 129 + k] = b_keys[idx];
    }
    __syncthreads();

    {
        int c = tid & 127, tg = tid >> 7;
        float acc[4];
        float bb = b_bq[c];
#pragma unroll
        for (int t = 0; t < 4; t++) acc[t] = bb;
        for (int i = 0; i < 256; i++) {
            float w = b_wq[i * 128 + c];
#pragma unroll
            for (int t = 0; t < 4; t++) acc[t] += s_x[(tg * 4 + t) * 256 + i] * w;
        }
#pragma unroll
        for (int t = 0; t < 4; t++) s_bq[(tg * 4 + t) * 128 + c] = acc[t];
    }
    __syncthreads();

    {
        const float invscale = 0.08838834764831845f;
        int t = tid >> 5, lane = tid & 31;
        float l0 = 0.f, l1 = 0.f;
        for (int k = 0; k < 128; k++) {
            float q = s_bq[t * 128 + k];
            l0 += q * s_keys[lane * 129 + k];
            l1 += q * s_keys[(lane + 32) * 129 + k];
        }
        l0 *= invscale; l1 *= invscale;
        float m = fmaxf(l0, l1);
#pragma unroll
        for (int o = 16; o > 0; o >>= 1) m = fmaxf(m, __shfl_xor_sync(0xffffffffu, m, o));
        float e0 = expf(l0 - m), e1 = expf(l1 - m);
        float ssum = e0 + e1;
#pragma unroll
        for (int o = 16; o > 0; o >>= 1) ssum += __shfl_xor_sync(0xffffffffu, ssum, o);
        float inv = 1.f / ssum;
        float* dst = g_ba + ((size_t)(t0 + t)) * 64;
        dst[lane] = e0 * inv;
        dst[lane + 32] = e1 * inv;
    }
}

// ---------------------------------------------------------------------------
// Kernel 2: recurrent core. 64 CTAs = 8 batches x cluster of 8.
// ---------------------------------------------------------------------------
__global__ __launch_bounds__(512, 1) __cluster_dims__(CLW, 1, 1)
void k_rec(
    const float* __restrict__ sb_init, const float* __restrict__ bp_b,
    const float* __restrict__ dn_bqkv, const float* __restrict__ dn_bbeta,
    const float* __restrict__ dn_bo, const float* __restrict__ dn_lng,
    const float* __restrict__ dn_lnb, const float* __restrict__ sup_b)
{
    extern __shared__ float sm[];
    __half* hs = (__half*)(sm + SM_HBASE);

    const int tid = threadIdx.x;
    const int b  = blockIdx.x / CLW;
    const int rk = blockIdx.x % CLW;
    const float invscale = 0.08838834764831845f;

    // ---- one-time init ----
    for (int idx = tid; idx < Nv * SDv; idx += 512) sm[SM_SLOTS + idx] = sb_init[idx];
    if (tid < 192) sm[SM_BQKV2 + tid] = dn_bqkv[(tid / 96) * 768 + rk * 96 + (tid % 96)];
    if (tid < 64)  sm[SM_BO2 + tid]   = dn_bo[(tid / 32) * 256 + rk * 32 + (tid % 32)];
    if (tid < 512) { sm[SM_LNG + tid] = dn_lng[tid]; sm[SM_LNB + tid] = dn_lnb[tid]; }
    if (tid < 32)  sm[SM_BPB2 + tid]  = bp_b[rk * 32 + tid];
    if (tid < 128) sm[SM_SUPB + tid]  = sup_b[tid];
    if (tid < 8)   sm[SM_BBETA + tid] = dn_bbeta[tid];
    if (tid == 0) {
        for (int i = 0; i < 12; i++) mbar_init(sm + SM_MBAR + i * 2, 1u);
    }

    {   // qkv slice: 6144 uint4
        const uint4* src = (const uint4*)(g_h + H_QKV);
        uint4* dst = (uint4*)(hs + WS_QKV);
        for (int i = tid; i < 6144; i += 512) {
            int rowL = i / 12, c = i % 12;
            dst[rowL * 12 + c] = src[(size_t)rowL * 96 + rk * 12 + c];
        }
    }
    {   // wo slice: 2048 uint4
        const uint4* src = (const uint4*)(g_h + H_WO);
        uint4* dst = (uint4*)(hs + WS_WO);
        for (int i = tid; i < 2048; i += 512) {
            int rowL = i / 4, c = i % 4;
            dst[rowL * 4 + c] = src[(size_t)rowL * 32 + rk * 4 + c];
        }
    }
    {   // bp slice: 512 uint4
        const uint4* src = (const uint4*)(g_h + H_BPW);
        uint4* dst = (uint4*)(hs + WS_BP);
        for (int i = tid; i < 512; i += 512) {
            int row = i / 4, c = i % 4;
            dst[row * 4 + c] = src[(size_t)row * 32 + rk * 4 + c];
        }
    }
    {   // sup slice: 512 uint4
        const uint4* src = (const uint4*)(g_h + H_SUPW);
        uint4* dst = (uint4*)(hs + WS_SUP);
        for (int i = tid; i < 512; i += 512) {
            int row = i / 2, c = i % 2;
            dst[row * 2 + c] = src[(size_t)row * 16 + rk * 2 + c];
        }
    }
    {   // wbeta replicated: 256 uint4
        const uint4* src = (const uint4*)(g_h + H_WBETA);
        uint4* dst = (uint4*)(hs + WS_BETA);
        for (int i = tid; i < 256; i += 512) dst[i] = src[i];
    }

    float Sreg[64];
#pragma unroll
    for (int j = 0; j < 64; j++) Sreg[j] = 0.f;
    const int l_own = tid >> 8;
    const int h_own = (tid >> 6) & 3;
    const int i_own = tid & 63;
    const int wp = tid >> 5, la = tid & 31;
    __syncthreads();
    cluster_sync_();   // mbarrier init visible cluster-wide

    // token prefetch registers (step 0)
    float pf_q = g_qwx[(size_t)(b * Sv) * 512 + tid];
    float pf_b = (tid < 64) ? g_ba[(size_t)(b * Sv) * 64 + tid] : 0.f;
    if (tid < 128) sm[SM_QN + tid] = pf_q;   // q0 for standalone logits at s=0

    for (int s = 0; s < Sv; ++s) {
        const size_t tok = (size_t)(b * Sv + s);
        const int set = s & 1;
        const unsigned par = (unsigned)((s >> 1) & 1);
        float* MB = sm + SM_MBAR + set * 2;

        // --- arm this step's barriers (tid 0) ---
        if (tid == 0) {
            mbar_expect(MB + 0 * 4, 1024u);   // bp
            mbar_expect(MB + 1 * 4, 3072u);   // qkv l0
            mbar_expect(MB + 2 * 4, 1024u);   // wo  l0
            mbar_expect(MB + 3 * 4, 3072u);   // qkv l1
            mbar_expect(MB + 4 * 4, 1024u);   // wo  l1
            mbar_expect(MB + 5 * 4, 512u);    // u
        }

        // --- A: commit prefetched token data ---
        if (tid >= 128 && tid < 256) sm[SM_WR + tid - 128] = pf_q;
        else if (tid >= 256) sm[SM_XH + tid - 256] = pf_q;
        if (tid < 64) {
            sm[SM_BA + tid] = pf_b;
            sm[SM_G2 + tid] = 1.f / (1.f + __expf(-pf_b));
        }
        __syncthreads();
        // prefetch next token
        if (s + 1 < Sv) {
            pf_q = g_qwx[(tok + 1) * 512 + tid];
            if (tid < 64) pf_b = g_ba[(tok + 1) * 64 + tid];
        }

        // --- preload D's slot operands ---
        float sv[16];
        {
            int d = tid & 127, ch = tid >> 7;
#pragma unroll
            for (int k = 0; k < 16; k++) sv[k] = sm[SM_SLOTS + (ch * 16 + k) * 128 + d];
        }

        // --- B (only s==0): standalone attn1 logits from SM_QN ---
        if (s == 0) {
#pragma unroll
            for (int r = 0; r < 4; r++) {
                int n = wp * 4 + r;
                const float* row = sm + SM_SLOTS + n * 128;
                float p = row[la] * sm[SM_QN + la] + row[la + 32] * sm[SM_QN + la + 32]
                        + row[la + 64] * sm[SM_QN + la + 64] + row[la + 96] * sm[SM_QN + la + 96];
#pragma unroll
                for (int o = 16; o > 0; o >>= 1) p += __shfl_xor_sync(0xffffffffu, p, o);
                if (la == 0) sm[SM_ABUF + n] = p * invscale;
            }
            __syncthreads();
        }

        // --- C: softmax + per-n coefficients (warp 0) ---
        if (tid < 32) {
            float l0 = sm[SM_ABUF + tid], l1 = sm[SM_ABUF + tid + 32];
            float m = fmaxf(l0, l1);
#pragma unroll
            for (int o = 16; o > 0; o >>= 1) m = fmaxf(m, __shfl_xor_sync(0xffffffffu, m, o));
            float e0 = __expf(l0 - m), e1 = __expf(l1 - m);
            float ss = e0 + e1;
#pragma unroll
            for (int o = 16; o > 0; o >>= 1) ss += __shfl_xor_sync(0xffffffffu, ss, o);
            float inv = 1.f / ss;
            float a0 = e0 * inv, a1 = e1 * inv;
            float g0 = 1.f / (1.f + __expf(-a0)), g1 = 1.f / (1.f + __expf(-a1));
            float ba0 = sm[SM_BA + tid], ba1 = sm[SM_BA + tid + 32];
            float g20 = sm[SM_G2 + tid], g21 = sm[SM_G2 + tid + 32];
            sm[SM_A + tid] = a0;  sm[SM_A + tid + 32] = a1;
            sm[SM_CB + tid] = ba0 * (1.f - g0);         sm[SM_CB + tid + 32] = ba1 * (1.f - g1);
            sm[SM_C1 + tid] = (1.f - g20) * (1.f - g0); sm[SM_C1 + tid + 32] = (1.f - g21) * (1.f - g1);
            sm[SM_C2 + tid] = (1.f - g20) * g0 * a0;    sm[SM_C2 + tid + 32] = (1.f - g21) * g1 * a1;
            sm[SM_T1 + tid] = g20 * ba0;                sm[SM_T1 + tid + 32] = g21 * ba1;
            float cw = ba0 * g0 * a0 + ba1 * g1 * a1;
#pragma unroll
            for (int o = 16; o > 0; o >>= 1) cw += __shfl_xor_sync(0xffffffffu, cw, o);
            if (tid == 0) sm[SM_MV + 2] = cw;
        }
        __syncthreads();

        // --- D: read (rk0 only) + bind partials from preloaded sv ---
        {
            int d = tid & 127, ch = tid >> 7;
            float pb0 = 0.f, pb1 = 0.f;
#pragma unroll
            for (int k = 0; k < 16; k += 2) {
                int n0 = ch * 16 + k;
                pb0 += sm[SM_CB + n0] * sv[k];
                pb1 += sm[SM_CB + n0 + 1] * sv[k + 1];
            }
            sm[SM_PART + 512 + ch * 128 + d] = pb0 + pb1;
            if (rk == 0) {
                float pr0 = 0.f, pr1 = 0.f;
#pragma unroll
                for (int k = 0; k < 16; k += 2) {
                    int n0 = ch * 16 + k;
                    pr0 += sm[SM_A + n0] * sv[k];
                    pr1 += sm[SM_A + n0 + 1] * sv[k + 1];
                }
                sm[SM_PART + ch * 128 + d] = pr0 + pr1;
            }
        }
        __syncthreads();
        // --- E: reduce read (export, rk0) + bind ---
        if (tid < 128) {
            if (rk == 0) {
                float rv = sm[SM_PART + tid] + sm[SM_PART + 128 + tid]
                         + sm[SM_PART + 256 + tid] + sm[SM_PART + 384 + tid];
                g_rx[tok * 384 + tid] = rv;
            }
            float bv = (sm[SM_PART + 512 + tid] + sm[SM_PART + 640 + tid])
                     + (sm[SM_PART + 768 + tid] + sm[SM_PART + 896 + tid])
                     + sm[SM_MV + 2] * sm[SM_WR + tid];
            sm[SM_BIND + tid] = bv;
        }
        __syncthreads();

        // --- F: bp GEMV ---
        if (tid < 128) {
            int cg = tid & 3, iseg = tid >> 2;
            const uint4* W = (const uint4*)(hs + WS_BP) + cg;
            float a0=0,a1=0,a2=0,a3=0,a4=0,a5=0,a6=0,a7=0;
#pragma unroll
            for (int r = 0; r < 4; r++) {
                int row = iseg + 32 * r;
                float xv = sm[SM_BIND + row];
                uint4 w = W[row * 4];
                FMA8(w, xv);
            }
            float* P = sm + SM_PART + iseg * 32 + cg * 8;
            P[0]=a0; P[1]=a1; P[2]=a2; P[3]=a3; P[4]=a4; P[5]=a5; P[6]=a6; P[7]=a7;
        }
        __syncthreads();
        // --- G: reduce + async exchange ---
        if (tid < 32) {
            float p0 = sm[SM_BPB2 + tid], p1 = 0.f, p2 = 0.f, p3 = 0.f;
#pragma unroll
            for (int sg = 0; sg < 32; sg += 4) {
                p0 += sm[SM_PART + sg * 32 + tid];
                p1 += sm[SM_PART + (sg + 1) * 32 + tid];
                p2 += sm[SM_PART + (sg + 2) * 32 + tid];
                p3 += sm[SM_PART + (sg + 3) * 32 + tid];
            }
            bcast_async(sm + SM_EXCH + set * 256 + rk * 32 + tid, MB + 0 * 4, (p0 + p1) + (p2 + p3));
        }
        mbar_wait(MB + 0 * 4, par);
        // --- H: xh += exch ---
        if (tid < 256) sm[SM_XH + tid] += sm[SM_EXCH + set * 256 + tid];
        __syncthreads();

        // --- DeltaNet layers ---
#pragma unroll
        for (int l = 0; l < 2; l++) {
            // I: qkv GEMV + beta
            if (tid < 384) {
                int cg = tid % 12, iseg = tid / 12;
                const uint4* W = (const uint4*)(hs + WS_QKV) + (size_t)l * 3072 + cg;
                float a0=0,a1=0,a2=0,a3=0,a4=0,a5=0,a6=0,a7=0;
#pragma unroll
                for (int r = 0; r < 8; r++) {
                    int row = iseg + 32 * r;
                    float xv = sm[SM_XH + row];
                    uint4 w = W[row * 12];
                    FMA8(w, xv);
                }
                float* P = sm + SM_PART + iseg * 96 + cg * 8;
                P[0]=a0; P[1]=a1; P[2]=a2; P[3]=a3; P[4]=a4; P[5]=a5; P[6]=a6; P[7]=a7;
            } else {
                int c = (tid - 384) >> 5;
                const __half* Wb = hs + WS_BETA + l * 1024;
                float acc = 0.f;
#pragma unroll
                for (int j = 0; j < 8; j++) {
                    int row = la + 32 * j;
                    acc += sm[SM_XH + row] * __half2float(Wb[row * 4 + c]);
                }
#pragma unroll
                for (int o = 16; o > 0; o >>= 1) acc += __shfl_xor_sync(0xffffffffu, acc, o);
                if (la == 0) {
                    float z = acc + sm[SM_BBETA + l * 4 + c];
                    sm[SM_BETA + c] = 1.f / (1.f + __expf(-z));
                }
            }
            __syncthreads();
            // J: reduce + async exchange qkv
            if (tid < 96) {
                float p0 = sm[SM_BQKV2 + l * 96 + tid], p1 = 0.f, p2 = 0.f, p3 = 0.f;
#pragma unroll
                for (int sg = 0; sg < 32; sg += 4) {
                    p0 += sm[SM_PART + sg * 96 + tid];
                    p1 += sm[SM_PART + (sg + 1) * 96 + tid];
                    p2 += sm[SM_PART + (sg + 2) * 96 + tid];
                    p3 += sm[SM_PART + (sg + 3) * 96 + tid];
                }
                bcast_async(sm + SM_QKV + set * 768 + rk * 96 + tid, MB + (1 + 2 * l) * 4, (p0 + p1) + (p2 + p3));
            }
            mbar_wait(MB + (1 + 2 * l) * 4, par);
            const float* qkvb = sm + SM_QKV + set * 768;

            // M: fused k-norm + state update (owners of layer l)
            if (l_own == l) {
                const float* kr = qkvb + 256 + h_own * 64;
                const float* qh = qkvb + h_own * 64;
                float n0 = 0.f, n1 = 0.f, n2 = 0.f, n3 = 0.f;
                float s0 = 0.f, s1 = 0.f, s2 = 0.f, s3 = 0.f;
#pragma unroll
                for (int j = 0; j < 64; j += 4) {
                    float k0 = kr[j], k1 = kr[j + 1], k2 = kr[j + 2], k3 = kr[j + 3];
                    n0 += k0 * k0; n1 += k1 * k1; n2 += k2 * k2; n3 += k3 * k3;
                    s0 += Sreg[j] * k0;     s1 += Sreg[j + 1] * k1;
                    s2 += Sreg[j + 2] * k2; s3 += Sreg[j + 3] * k3;
                }
                float inv = 1.f / (sqrtf((n0 + n1) + (n2 + n3)) + 1e-6f);
                float sk = ((s0 + s1) + (s2 + s3)) * inv;
                float delta = sm[SM_BETA + h_own] * (qkvb[512 + h_own * 64 + i_own] - sk);
                float d2 = delta * inv;
                float o0 = 0.f, o1 = 0.f, o2 = 0.f, o3 = 0.f;
#pragma unroll
                for (int j = 0; j < 64; j += 4) {
                    Sreg[j]     += d2 * kr[j];     o0 += Sreg[j] * qh[j];
                    Sreg[j + 1] += d2 * kr[j + 1]; o1 += Sreg[j + 1] * qh[j + 1];
                    Sreg[j + 2] += d2 * kr[j + 2]; o2 += Sreg[j + 2] * qh[j + 2];
                    Sreg[j + 3] += d2 * kr[j + 3]; o3 += Sreg[j + 3] * qh[j + 3];
                }
                sm[SM_O + h_own * 64 + i_own] = (o0 + o1) + (o2 + o3);
            }
            __syncthreads();
            // N: wo GEMV
            if (tid < 256) {
                int cg = tid & 3, iseg = tid >> 2;
                const uint4* W = (const uint4*)(hs + WS_WO) + (size_t)l * 1024 + cg;
                float a0=0,a1=0,a2=0,a3=0,a4=0,a5=0,a6=0,a7=0;
#pragma unroll
                for (int r = 0; r < 4; r++) {
                    int row = iseg + 64 * r;
                    float xv = sm[SM_O + row];
                    uint4 w = W[row * 4];
                    FMA8(w, xv);
                }
                float* P = sm + SM_PART + iseg * 32 + cg * 8;
                P[0]=a0; P[1]=a1; P[2]=a2; P[3]=a3; P[4]=a4; P[5]=a5; P[6]=a6; P[7]=a7;
            }
            __syncthreads();
            // O: reduce + async exchange
            if (tid < 32) {
                float p0 = sm[SM_BO2 + l * 32 + tid], p1 = 0.f, p2 = 0.f, p3 = 0.f;
#pragma unroll
                for (int sg = 0; sg < 64; sg += 4) {
                    p0 += sm[SM_PART + sg * 32 + tid];
                    p1 += sm[SM_PART + (sg + 1) * 32 + tid];
                    p2 += sm[SM_PART + (sg + 2) * 32 + tid];
                    p3 += sm[SM_PART + (sg + 3) * 32 + tid];
                }
                bcast_async(sm + SM_WOUT + set * 256 + rk * 32 + tid, MB + (2 + 2 * l) * 4, (p0 + p1) + (p2 + p3));
            }
            mbar_wait(MB + (2 + 2 * l) * 4, par);
            const float* woutb = sm + SM_WOUT + set * 256;

            // Q: LN stats from xh+wout (warp 0)
            if (tid < 32) {
                float s1 = 0.f, s2 = 0.f;
#pragma unroll
                for (int k = 0; k < 8; k++) {
                    float v = sm[SM_XH + tid * 8 + k] + woutb[tid * 8 + k];
                    s1 += v; s2 += v * v;
                }
#pragma unroll
                for (int o = 16; o > 0; o >>= 1) {
                    s1 += __shfl_xor_sync(0xffffffffu, s1, o);
                    s2 += __shfl_xor_sync(0xffffffffu, s2, o);
                }
                if (tid == 0) {
                    float m = s1 / 256.f;
                    float var = s2 / 256.f - m * m;
                    sm[SM_MV + 0] = m; sm[SM_MV + 1] = rsqrtf(var + 1e-5f);
                }
            }
            __syncthreads();
            // R: normalize (resid inline)
            if (tid < 256) {
                float r = sm[SM_XH + tid] + woutb[tid];
                sm[SM_XH + tid] = (r - sm[SM_MV + 0]) * sm[SM_MV + 1]
                                * sm[SM_LNG + l * 256 + tid] + sm[SM_LNB + l * 256 + tid];
            }
            __syncthreads();
        }

        // --- S: sup GEMV + stage q_{s+1} + xh export (rk0) ---
        if (tid < 128) {
            sm[SM_QN + tid] = pf_q;   // next-token q for fused logits in U
            int cg = tid & 1, iseg = tid >> 1;
            const uint4* W = (const uint4*)(hs + WS_SUP) + cg;
            float a0=0,a1=0,a2=0,a3=0,a4=0,a5=0,a6=0,a7=0;
#pragma unroll
            for (int r = 0; r < 4; r++) {
                int row = iseg + 64 * r;
                float xv = sm[SM_XH + row];
                uint4 w = W[row * 2];
                FMA8(w, xv);
            }
            float* P = sm + SM_PART + iseg * 16 + cg * 8;
            P[0]=a0; P[1]=a1; P[2]=a2; P[3]=a3; P[4]=a4; P[5]=a5; P[6]=a6; P[7]=a7;
        } else if (tid >= 256 && rk == 0) {
            g_rx[tok * 384 + 128 + (tid - 256)] = sm[SM_XH + tid - 256];
        }
        __syncthreads();
        // --- T: reduce + async exchange u ---
        if (tid < 16) {
            float p0 = 0.f, p1 = 0.f, p2 = 0.f, p3 = 0.f;
#pragma unroll
            for (int sg = 0; sg < 64; sg += 4) {
                p0 += sm[SM_PART + sg * 16 + tid];
                p1 += sm[SM_PART + (sg + 1) * 16 + tid];
                p2 += sm[SM_PART + (sg + 2) * 16 + tid];
                p3 += sm[SM_PART + (sg + 3) * 16 + tid];
            }
            bcast_async(sm + SM_U + set * 128 + rk * 16 + tid, MB + 5 * 4, (p0 + p1) + (p2 + p3));
        }
        // --- U pass 1 (pre-wait): slot partial update c1*s + c2*wr + g2*supb ---
        // Hides the u-exchange round-trip behind slot FMAs. Each element is
        // owned by exactly one thread across both passes (no sync needed).
        {
            float w0 = sm[SM_WR + la],       w1 = sm[SM_WR + la + 32],
                  w2 = sm[SM_WR + la + 64],  w3 = sm[SM_WR + la + 96];
            float b0 = sm[SM_SUPB + la],      b1 = sm[SM_SUPB + la + 32],
                  b2 = sm[SM_SUPB + la + 64], b3 = sm[SM_SUPB + la + 96];
#pragma unroll
            for (int r = 0; r < 4; r++) {
                int n = wp * 4 + r;
                float c1 = sm[SM_C1 + n], c2 = sm[SM_C2 + n], g2 = sm[SM_G2 + n];
                float* row = sm + SM_SLOTS + n * 128;
                row[la]      = c1 * row[la]      + c2 * w0 + g2 * b0;
                row[la + 32] = c1 * row[la + 32] + c2 * w1 + g2 * b1;
                row[la + 64] = c1 * row[la + 64] + c2 * w2 + g2 * b2;
                row[la + 96] = c1 * row[la + 96] + c2 * w3 + g2 * b3;
            }
        }
        mbar_wait(MB + 5 * 4, par);
        // --- U pass 2 (post-wait): += t1*u, store, fused next-step logits ---
        {
            const float* ub = sm + SM_U + set * 128;
            float u0 = ub[la],      u1 = ub[la + 32],
                  u2 = ub[la + 64], u3 = ub[la + 96];
            float q0 = sm[SM_QN + la],      q1 = sm[SM_QN + la + 32],
                  q2 = sm[SM_QN + la + 64], q3 = sm[SM_QN + la + 96];
#pragma unroll
            for (int r = 0; r < 4; r++) {
                int n = wp * 4 + r;
                float t1 = sm[SM_T1 + n];
                float* row = sm + SM_SLOTS + n * 128;
                float s0 = row[la]      + t1 * u0;
                float s1 = row[la + 32] + t1 * u1;
                float s2 = row[la + 64] + t1 * u2;
                float s3 = row[la + 96] + t1 * u3;
                row[la] = s0; row[la + 32] = s1; row[la + 64] = s2; row[la + 96] = s3;
                float p = s0 * q0 + s1 * q1 + s2 * q2 + s3 * q3;
#pragma unroll
                for (int o = 16; o > 0; o >>= 1) p += __shfl_xor_sync(0xffffffffu, p, o);
                if (la == 0) sm[SM_ABUF + n] = p * invscale;
            }
        }
        __syncthreads();
    }
    cluster_sync_();   // keep cluster resident until all remote stores landed
}

// ---------------------------------------------------------------------------
__global__ __launch_bounds__(512) void k_out(
    const float* __restrict__ sb_wo, const float* __restrict__ sb_bo,
    const float* __restrict__ op_w, const float* __restrict__ op_b,
    const float* __restrict__ oln_g, const float* __restrict__ oln_b,
    const float* __restrict__ ow, const float* __restrict__ ob,
    float* __restrict__ out)
{
    __shared__ float rx[8 * 384];
    __shared__ float yt[8 * 512];
    __shared__ float mv[8][2];
    const int t0 = blockIdx.x * 8;
    const int tid = threadIdx.x;
    const float* src = g_rx + (size_t)t0 * 384;
    for (int idx = tid; idx < 8 * 384; idx += 512) rx[idx] = src[idx];
    __syncthreads();

    {
        float acc[8];
        float bias = sb_bo[tid] + op_b[tid];
#pragma unroll
        for (int t = 0; t < 8; t++) acc[t] = bias;
        const float* w1 = sb_wo + tid;
        for (int i = 0; i < 128; i++) {
            float wv = w1[(size_t)i * 512];
#pragma unroll
            for (int t = 0; t < 8; t++) acc[t] += rx[t * 384 + i] * wv;
        }
        const float* w2 = op_w + tid;
        for (int i = 0; i < 256; i++) {
            float wv = w2[(size_t)i * 512];
#pragma unroll
            for (int t = 0; t < 8; t++) acc[t] += rx[t * 384 + 128 + i] * wv;
        }
#pragma unroll
        for (int t = 0; t < 8; t++) yt[t * 512 + tid] = acc[t];
    }
    __syncthreads();

    if (tid < 256) {
        int tt = tid >> 5, lane = tid & 31;
        float s1 = 0.f, s2 = 0.f;
        for (int i = lane; i < 512; i += 32) { float v = yt[tt * 512 + i]; s1 += v; s2 += v * v; }
#pragma unroll
        for (int o = 16; o > 0; o >>= 1) {
            s1 += __shfl_xor_sync(0xffffffffu, s1, o);
            s2 += __shfl_xor_sync(0xffffffffu, s2, o);
        }
        if (lane == 0) {
            float m = s1 / 512.f;
            mv[tt][0] = m;
            mv[tt][1] = rsqrtf(s2 / 512.f - m * m + 1e-5f);
        }
    }
    __syncthreads();
    for (int idx = tid; idx < 8 * 512; idx += 512) {
        int tt = idx >> 9, c = idx & 511;
        yt[idx] = (yt[idx] - mv[tt][0]) * mv[tt][1] * oln_g[c] + oln_b[c];
    }
    __syncthreads();

    float acc[8];
#pragma unroll
    for (int t = 0; t < 8; t++) acc[t] = ob[tid];
    const float* w = ow + tid;
    for (int i = 0; i < 512; i++) {
        float wv = w[(size_t)i * 512];
#pragma unroll
        for (int t = 0; t < 8; t++) acc[t] += yt[t * 512 + i] * wv;
    }
    float* dst = out + (size_t)t0 * 512;
#pragma unroll
    for (int t = 0; t < 8; t++) dst[t * 512 + tid] = acc[t];
}

// ---------------------------------------------------------------------------
extern "C" void kernel_launch(void* const* d_in, const int* in_sizes, int n_in,
                              void* d_out, int out_size)
{
    const float* x        = (const float*)d_in[0];
    const float* sb_init  = (const float*)d_in[1];
    const float* sb_wq    = (const float*)d_in[2];
    const float* sb_bq    = (const float*)d_in[3];
    const float* sb_ww    = (const float*)d_in[4];
    const float* sb_bw    = (const float*)d_in[5];
    const float* sb_wo    = (const float*)d_in[6];
    const float* sb_bo    = (const float*)d_in[7];
    const float* p_win    = (const float*)d_in[8];
    const float* p_bin    = (const float*)d_in[9];
    const float* b_wq     = (const float*)d_in[10];
    const float* b_bq     = (const float*)d_in[11];
    const float* b_keys   = (const float*)d_in[12];
    const float* bp_w     = (const float*)d_in[13];
    const float* bp_b     = (const float*)d_in[14];
    const float* dn_wqkv  = (const float*)d_in[15];
    const float* dn_bqkv  = (const float*)d_in[16];
    const float* dn_wbeta = (const float*)d_in[17];
    const float* dn_bbeta = (const float*)d_in[18];
    const float* dn_wo    = (const float*)d_in[19];
    const float* dn_bo    = (const float*)d_in[20];
    const float* dn_lng   = (const float*)d_in[21];
    const float* dn_lnb   = (const float*)d_in[22];
    const float* sup_w    = (const float*)d_in[23];
    const float* sup_b    = (const float*)d_in[24];
    const float* op_w     = (const float*)d_in[25];
    const float* op_b     = (const float*)d_in[26];
    const float* oln_g    = (const float*)d_in[27];
    const float* oln_b    = (const float*)d_in[28];
    const float* ow       = (const float*)d_in[29];
    const float* ob       = (const float*)d_in[30];

    static bool attr_set = false;
    if (!attr_set) {
        cudaFuncSetAttribute(k_rec, cudaFuncAttributeMaxDynamicSharedMemorySize, SMEM_REC_BYTES);
        attr_set = true;
    }

    k_cvt<<<(H_TOTAL + 511) / 512, 512>>>(dn_wqkv, dn_wo, bp_w, sup_w, dn_wbeta);
    k_pre<<<512, 512>>>(x, sb_wq, sb_bq, sb_ww, sb_bw, p_win, p_bin);
    k_ba<<<1024, 256>>>(b_wq, b_bq, b_keys);
    k_rec<<<Bv * CLW, 512, SMEM_REC_BYTES>>>(sb_init, bp_b, dn_bqkv, dn_bbeta, dn_bo,
                                             dn_lng, dn_lnb, sup_b);
    k_out<<<1024, 512>>>(sb_wo, sb_bo, op_w, op_b, oln_g, oln_b, ow, ob, (float*)d_out);
}

// round 16
// speedup vs baseline: 1.0086x; 1.0086x over previous
#include <cuda_runtime.h>
#include <cuda_fp16.h>
#include <cstdint>
#include <math.h>

#define Bv 8
#define Sv 1024
#define Dv 512
#define Hv 256
#define Nv 64
#define SDv 128
#define NHv 4
#define DHv 64

#define CLW 8   // cluster width (ranks per batch)

// ---- device scratch (no allocations allowed) ----
__device__ float g_qwx[(size_t)Bv * Sv * 512];   // per token: [q(128) | wr(128) | xh0(256)]
__device__ float g_ba[(size_t)Bv * Sv * 64];     // precomputed attn2 softmax
__device__ float g_rx[(size_t)Bv * Sv * 384];    // per token: [read(128) | xh_final(256)]
__device__ __align__(256) __half g_h[591872];    // fp16 weight pack

#define H_QKV   0          // 2*256*768 = 393216
#define H_WO    393216     // 2*256*256 = 131072
#define H_BPW   524288     // 128*256   = 32768
#define H_SUPW  557056     // 256*128   = 32768
#define H_WBETA 589824     // 2*256*4   = 2048
#define H_TOTAL 591872

// smem float-index layout for k_rec
#define SM_SLOTS 0        // 8192
#define SM_PART  8192     // 3072
#define SM_QN    11264    // 128  (next-token q for fused logits)
#define SM_WR    11392    // 128
#define SM_XH    11520    // 256
#define SM_ABUF  11776    // 64
#define SM_A     11840    // 64
#define SM_BA    11904    // 64
#define SM_G2    11968    // 64
#define SM_CB    12032    // 64
#define SM_C1    12096    // 64
#define SM_C2    12160    // 64
#define SM_T1    12224    // 64
#define SM_BIND  12288    // 128
#define SM_QKV   12416    // 1536 = 2 sets x 768
#define SM_BETA  14208    // 4
#define SM_O     14212    // 256
#define SM_U     14468    // 256 = 2 x 128
#define SM_EXCH  14724    // 512 = 2 x 256
#define SM_WOUT  15236    // 512 = 2 x 256
#define SM_MV    15748    // 4
#define SM_BQKV2 15752    // 192
#define SM_BO2   15944    // 64
#define SM_LNG   16008    // 512
#define SM_LNB   16520    // 512
#define SM_BPB2  17032    // 32
#define SM_SUPB  17064    // 128
#define SM_BBETA 17192    // 8
#define SM_MBAR  17200    // 24 floats = 12 u64 mbarriers
#define SM_STAT  17224    // 32 floats = 2 sets x 8 ranks x {s1,s2}
#define SM_HBASE 17256    // halves start (byte 69024, 16B aligned)
// half offsets (relative to half base)
#define WS_QKV  0         // 2*256*96 = 49152
#define WS_WO   49152     // 2*256*32 = 16384
#define WS_BP   65536     // 128*32   = 4096
#define WS_SUP  69632     // 256*16   = 4096
#define WS_BETA 73728     // 2*256*4  = 2048
#define SMEM_REC_BYTES (SM_HBASE * 4 + 75776 * 2)   // 220576

// ---- cluster / mbarrier helpers ----
__device__ __forceinline__ void cluster_sync_() {
    asm volatile("barrier.cluster.arrive.aligned;" ::: "memory");
    asm volatile("barrier.cluster.wait.aligned;" ::: "memory");
}
__device__ __forceinline__ void mbar_init(float* lmbar, unsigned cnt) {
    unsigned m = (unsigned)__cvta_generic_to_shared(lmbar);
    asm volatile("mbarrier.init.shared.b64 [%0], %1;" :: "r"(m), "r"(cnt) : "memory");
}
__device__ __forceinline__ void mbar_expect(float* lmbar, unsigned tx) {
    unsigned m = (unsigned)__cvta_generic_to_shared(lmbar);
    asm volatile("mbarrier.arrive.expect_tx.shared.b64 _, [%0], %1;" :: "r"(m), "r"(tx) : "memory");
}
// bounded-spin wait: never hangs the container
__device__ __forceinline__ void mbar_wait(float* lmbar, unsigned parity) {
    unsigned m = (unsigned)__cvta_generic_to_shared(lmbar);
    unsigned done = 0;
    long long t0 = clock64();
    while (!done) {
        asm volatile("{\n\t.reg .pred P;\n\t"
            "mbarrier.try_wait.parity.acquire.cluster.shared::cta.b64 P, [%1], %2, 0x989680;\n\t"
            "selp.b32 %0, 1, 0, P;\n\t}"
            : "=r"(done) : "r"(m), "r"(parity) : "memory");
        if (!done && (clock64() - t0) > 200000000LL) break;   // ~0.1 s watchdog
    }
}
__device__ __forceinline__ void st_async_f32(float* lptr, float* lmbar, int rr, float v) {
    unsigned a = (unsigned)__cvta_generic_to_shared(lptr);
    unsigned m = (unsigned)__cvta_generic_to_shared(lmbar);
    unsigned ra, rm;
    asm volatile("mapa.shared::cluster.u32 %0, %1, %2;" : "=r"(ra) : "r"(a), "r"(rr));
    asm volatile("mapa.shared::cluster.u32 %0, %1, %2;" : "=r"(rm) : "r"(m), "r"(rr));
    asm volatile("st.async.shared::cluster.mbarrier::complete_tx::bytes.b32 [%0], %1, [%2];"
                 :: "r"(ra), "r"(__float_as_uint(v)), "r"(rm) : "memory");
}
__device__ __forceinline__ void bcast_async(float* lptr, float* lmbar, float v) {
#pragma unroll
    for (int rr = 0; rr < CLW; rr++) st_async_f32(lptr, lmbar, rr, v);
}

// fp16 vec8 FMA helper
#define FMA8(w, xv) do { \
    half2 h0 = *(half2*)&(w).x, h1 = *(half2*)&(w).y, h2 = *(half2*)&(w).z, h3 = *(half2*)&(w).w; \
    a0 += (xv) * __low2float(h0); a1 += (xv) * __high2float(h0); \
    a2 += (xv) * __low2float(h1); a3 += (xv) * __high2float(h1); \
    a4 += (xv) * __low2float(h2); a5 += (xv) * __high2float(h2); \
    a6 += (xv) * __low2float(h3); a7 += (xv) * __high2float(h3); } while (0)

// ---------------------------------------------------------------------------
__global__ __launch_bounds__(512) void k_cvt(
    const float* __restrict__ wqkv, const float* __restrict__ wo,
    const float* __restrict__ bpw, const float* __restrict__ supw,
    const float* __restrict__ wbeta)
{
    int i = blockIdx.x * 512 + threadIdx.x;
    if (i >= H_TOTAL) return;
    float v;
    if (i < H_WO)        v = wqkv[i];
    else if (i < H_BPW)  v = wo[i - H_WO];
    else if (i < H_SUPW) v = bpw[i - H_BPW];
    else if (i < H_WBETA) v = supw[i - H_SUPW];
    else                 v = wbeta[i - H_WBETA];
    g_h[i] = __float2half(v);
}

// ---------------------------------------------------------------------------
__global__ __launch_bounds__(512) void k_pre(
    const float* __restrict__ x,
    const float* __restrict__ sb_wq, const float* __restrict__ sb_bq,
    const float* __restrict__ sb_ww, const float* __restrict__ sb_bw,
    const float* __restrict__ p_win, const float* __restrict__ p_bin)
{
    __shared__ float xs[16 * 512];
    const int t0 = blockIdx.x * 16;
    const int tid = threadIdx.x;
    const float* xb = x + (size_t)t0 * 512;
    for (int idx = tid; idx < 16 * 512; idx += 512) xs[idx] = xb[idx];
    __syncthreads();

    const int c = tid;
    const float* W; int ld; float bias;
    if (c < 128)      { W = sb_wq + c;         ld = 128; bias = sb_bq[c]; }
    else if (c < 256) { W = sb_ww + (c - 128); ld = 128; bias = sb_bw[c - 128]; }
    else              { W = p_win + (c - 256); ld = 256; bias = p_bin[c - 256]; }

    float acc[16];
#pragma unroll
    for (int t = 0; t < 16; t++) acc[t] = 0.f;
    for (int i = 0; i < 512; i++) {
        float w = W[(size_t)i * ld];
#pragma unroll
        for (int t = 0; t < 16; t++) acc[t] += xs[t * 512 + i] * w;
    }
#pragma unroll
    for (int t = 0; t < 16; t++)
        g_qwx[((size_t)(t0 + t)) * 512 + c] = acc[t] + bias;
}

// ---------------------------------------------------------------------------
__global__ __launch_bounds__(256) void k_ba(
    const float* __restrict__ b_wq, const float* __restrict__ b_bq,
    const float* __restrict__ b_keys)
{
    __shared__ float s_x[8 * 256];
    __shared__ float s_keys[64 * 129];
    __shared__ float s_bq[8 * 128];
    const int t0 = blockIdx.x * 8;
    const int tid = threadIdx.x;

    for (int idx = tid; idx < 8 * 256; idx += 256) {
        int t = idx >> 8, i = idx & 255;
        s_x[idx] = g_qwx[((size_t)(t0 + t)) * 512 + 256 + i];
    }
    for (int idx = tid; idx < 64 * 128; idx += 256) {
        int n = idx >> 7, k = idx & 127;
        s_keys[n * 129 + k] = b_keys[idx];
    }
    __syncthreads();

    {
        int c = tid & 127, tg = tid >> 7;
        float acc[4];
        float bb = b_bq[c];
#pragma unroll
        for (int t = 0; t < 4; t++) acc[t] = bb;
        for (int i = 0; i < 256; i++) {
            float w = b_wq[i * 128 + c];
#pragma unroll
            for (int t = 0; t < 4; t++) acc[t] += s_x[(tg * 4 + t) * 256 + i] * w;
        }
#pragma unroll
        for (int t = 0; t < 4; t++) s_bq[(tg * 4 + t) * 128 + c] = acc[t];
    }
    __syncthreads();

    {
        const float invscale = 0.08838834764831845f;
        int t = tid >> 5, lane = tid & 31;
        float l0 = 0.f, l1 = 0.f;
        for (int k = 0; k < 128; k++) {
            float q = s_bq[t * 128 + k];
            l0 += q * s_keys[lane * 129 + k];
            l1 += q * s_keys[(lane + 32) * 129 + k];
        }
        l0 *= invscale; l1 *= invscale;
        float m = fmaxf(l0, l1);
#pragma unroll
        for (int o = 16; o > 0; o >>= 1) m = fmaxf(m, __shfl_xor_sync(0xffffffffu, m, o));
        float e0 = expf(l0 - m), e1 = expf(l1 - m);
        float ssum = e0 + e1;
#pragma unroll
        for (int o = 16; o > 0; o >>= 1) ssum += __shfl_xor_sync(0xffffffffu, ssum, o);
        float inv = 1.f / ssum;
        float* dst = g_ba + ((size_t)(t0 + t)) * 64;
        dst[lane] = e0 * inv;
        dst[lane + 32] = e1 * inv;
    }
}

// ---------------------------------------------------------------------------
// Kernel 2: recurrent core. 64 CTAs = 8 batches x cluster of 8.
// LN stats piggybacked on the wo exchange (no separate stats phase).
// ---------------------------------------------------------------------------
__global__ __launch_bounds__(512, 1) __cluster_dims__(CLW, 1, 1)
void k_rec(
    const float* __restrict__ sb_init, const float* __restrict__ bp_b,
    const float* __restrict__ dn_bqkv, const float* __restrict__ dn_bbeta,
    const float* __restrict__ dn_bo, const float* __restrict__ dn_lng,
    const float* __restrict__ dn_lnb, const float* __restrict__ sup_b)
{
    extern __shared__ float sm[];
    __half* hs = (__half*)(sm + SM_HBASE);

    const int tid = threadIdx.x;
    const int b  = blockIdx.x / CLW;
    const int rk = blockIdx.x % CLW;
    const float invscale = 0.08838834764831845f;

    // ---- one-time init ----
    for (int idx = tid; idx < Nv * SDv; idx += 512) sm[SM_SLOTS + idx] = sb_init[idx];
    if (tid < 192) sm[SM_BQKV2 + tid] = dn_bqkv[(tid / 96) * 768 + rk * 96 + (tid % 96)];
    if (tid < 64)  sm[SM_BO2 + tid]   = dn_bo[(tid / 32) * 256 + rk * 32 + (tid % 32)];
    if (tid < 512) { sm[SM_LNG + tid] = dn_lng[tid]; sm[SM_LNB + tid] = dn_lnb[tid]; }
    if (tid < 32)  sm[SM_BPB2 + tid]  = bp_b[rk * 32 + tid];
    if (tid < 128) sm[SM_SUPB + tid]  = sup_b[tid];
    if (tid < 8)   sm[SM_BBETA + tid] = dn_bbeta[tid];
    if (tid == 0) {
        for (int i = 0; i < 12; i++) mbar_init(sm + SM_MBAR + i * 2, 1u);
    }

    {   // qkv slice: 6144 uint4
        const uint4* src = (const uint4*)(g_h + H_QKV);
        uint4* dst = (uint4*)(hs + WS_QKV);
        for (int i = tid; i < 6144; i += 512) {
            int rowL = i / 12, c = i % 12;
            dst[rowL * 12 + c] = src[(size_t)rowL * 96 + rk * 12 + c];
        }
    }
    {   // wo slice: 2048 uint4
        const uint4* src = (const uint4*)(g_h + H_WO);
        uint4* dst = (uint4*)(hs + WS_WO);
        for (int i = tid; i < 2048; i += 512) {
            int rowL = i / 4, c = i % 4;
            dst[rowL * 4 + c] = src[(size_t)rowL * 32 + rk * 4 + c];
        }
    }
    {   // bp slice: 512 uint4
        const uint4* src = (const uint4*)(g_h + H_BPW);
        uint4* dst = (uint4*)(hs + WS_BP);
        for (int i = tid; i < 512; i += 512) {
            int row = i / 4, c = i % 4;
            dst[row * 4 + c] = src[(size_t)row * 32 + rk * 4 + c];
        }
    }
    {   // sup slice: 512 uint4
        const uint4* src = (const uint4*)(g_h + H_SUPW);
        uint4* dst = (uint4*)(hs + WS_SUP);
        for (int i = tid; i < 512; i += 512) {
            int row = i / 2, c = i % 2;
            dst[row * 2 + c] = src[(size_t)row * 16 + rk * 2 + c];
        }
    }
    {   // wbeta replicated: 256 uint4
        const uint4* src = (const uint4*)(g_h + H_WBETA);
        uint4* dst = (uint4*)(hs + WS_BETA);
        for (int i = tid; i < 256; i += 512) dst[i] = src[i];
    }

    float Sreg[64];
#pragma unroll
    for (int j = 0; j < 64; j++) Sreg[j] = 0.f;
    const int l_own = tid >> 8;
    const int h_own = (tid >> 6) & 3;
    const int i_own = tid & 63;
    const int wp = tid >> 5, la = tid & 31;
    __syncthreads();
    cluster_sync_();   // mbarrier init visible cluster-wide

    // token prefetch registers (step 0)
    float pf_q = g_qwx[(size_t)(b * Sv) * 512 + tid];
    float pf_b = (tid < 64) ? g_ba[(size_t)(b * Sv) * 64 + tid] : 0.f;
    if (tid < 128) sm[SM_QN + tid] = pf_q;   // q0 for standalone logits at s=0

    for (int s = 0; s < Sv; ++s) {
        const size_t tok = (size_t)(b * Sv + s);
        const int set = s & 1;
        const unsigned par = (unsigned)((s >> 1) & 1);
        float* MB = sm + SM_MBAR + set * 2;

        // --- arm this step's barriers (tid 0) ---
        if (tid == 0) {
            mbar_expect(MB + 0 * 4, 1024u);   // bp
            mbar_expect(MB + 1 * 4, 3072u);   // qkv l0
            mbar_expect(MB + 2 * 4, 1088u);   // wo l0 + stats
            mbar_expect(MB + 3 * 4, 3072u);   // qkv l1
            mbar_expect(MB + 4 * 4, 1088u);   // wo l1 + stats
            mbar_expect(MB + 5 * 4, 512u);    // u
        }

        // --- A: commit prefetched token data ---
        if (tid >= 128 && tid < 256) sm[SM_WR + tid - 128] = pf_q;
        else if (tid >= 256) sm[SM_XH + tid - 256] = pf_q;
        if (tid < 64) {
            sm[SM_BA + tid] = pf_b;
            sm[SM_G2 + tid] = 1.f / (1.f + __expf(-pf_b));
        }
        __syncthreads();
        // prefetch next token
        if (s + 1 < Sv) {
            pf_q = g_qwx[(tok + 1) * 512 + tid];
            if (tid < 64) pf_b = g_ba[(tok + 1) * 64 + tid];
        }

        // --- preload D's slot operands ---
        float sv[16];
        {
            int d = tid & 127, ch = tid >> 7;
#pragma unroll
            for (int k = 0; k < 16; k++) sv[k] = sm[SM_SLOTS + (ch * 16 + k) * 128 + d];
        }

        // --- B (only s==0): standalone attn1 logits from SM_QN ---
        if (s == 0) {
#pragma unroll
            for (int r = 0; r < 4; r++) {
                int n = wp * 4 + r;
                const float* row = sm + SM_SLOTS + n * 128;
                float p = row[la] * sm[SM_QN + la] + row[la + 32] * sm[SM_QN + la + 32]
                        + row[la + 64] * sm[SM_QN + la + 64] + row[la + 96] * sm[SM_QN + la + 96];
#pragma unroll
                for (int o = 16; o > 0; o >>= 1) p += __shfl_xor_sync(0xffffffffu, p, o);
                if (la == 0) sm[SM_ABUF + n] = p * invscale;
            }
            __syncthreads();
        }

        // --- C: softmax + per-n coefficients (warp 0) ---
        if (tid < 32) {
            float l0 = sm[SM_ABUF + tid], l1 = sm[SM_ABUF + tid + 32];
            float m = fmaxf(l0, l1);
#pragma unroll
            for (int o = 16; o > 0; o >>= 1) m = fmaxf(m, __shfl_xor_sync(0xffffffffu, m, o));
            float e0 = __expf(l0 - m), e1 = __expf(l1 - m);
            float ss = e0 + e1;
#pragma unroll
            for (int o = 16; o > 0; o >>= 1) ss += __shfl_xor_sync(0xffffffffu, ss, o);
            float inv = 1.f / ss;
            float a0 = e0 * inv, a1 = e1 * inv;
            float g0 = 1.f / (1.f + __expf(-a0)), g1 = 1.f / (1.f + __expf(-a1));
            float ba0 = sm[SM_BA + tid], ba1 = sm[SM_BA + tid + 32];
            float g20 = sm[SM_G2 + tid], g21 = sm[SM_G2 + tid + 32];
            sm[SM_A + tid] = a0;  sm[SM_A + tid + 32] = a1;
            sm[SM_CB + tid] = ba0 * (1.f - g0);         sm[SM_CB + tid + 32] = ba1 * (1.f - g1);
            sm[SM_C1 + tid] = (1.f - g20) * (1.f - g0); sm[SM_C1 + tid + 32] = (1.f - g21) * (1.f - g1);
            sm[SM_C2 + tid] = (1.f - g20) * g0 * a0;    sm[SM_C2 + tid + 32] = (1.f - g21) * g1 * a1;
            sm[SM_T1 + tid] = g20 * ba0;                sm[SM_T1 + tid + 32] = g21 * ba1;
            float cw = ba0 * g0 * a0 + ba1 * g1 * a1;
#pragma unroll
            for (int o = 16; o > 0; o >>= 1) cw += __shfl_xor_sync(0xffffffffu, cw, o);
            if (tid == 0) sm[SM_MV + 2] = cw;
        }
        __syncthreads();

        // --- D: read (rk0 only) + bind partials from preloaded sv ---
        {
            int d = tid & 127, ch = tid >> 7;
            float pb0 = 0.f, pb1 = 0.f;
#pragma unroll
            for (int k = 0; k < 16; k += 2) {
                int n0 = ch * 16 + k;
                pb0 += sm[SM_CB + n0] * sv[k];
                pb1 += sm[SM_CB + n0 + 1] * sv[k + 1];
            }
            sm[SM_PART + 512 + ch * 128 + d] = pb0 + pb1;
            if (rk == 0) {
                float pr0 = 0.f, pr1 = 0.f;
#pragma unroll
                for (int k = 0; k < 16; k += 2) {
                    int n0 = ch * 16 + k;
                    pr0 += sm[SM_A + n0] * sv[k];
                    pr1 += sm[SM_A + n0 + 1] * sv[k + 1];
                }
                sm[SM_PART + ch * 128 + d] = pr0 + pr1;
            }
        }
        __syncthreads();
        // --- E: reduce read (export, rk0) + bind ---
        if (tid < 128) {
            if (rk == 0) {
                float rv = sm[SM_PART + tid] + sm[SM_PART + 128 + tid]
                         + sm[SM_PART + 256 + tid] + sm[SM_PART + 384 + tid];
                g_rx[tok * 384 + tid] = rv;
            }
            float bv = (sm[SM_PART + 512 + tid] + sm[SM_PART + 640 + tid])
                     + (sm[SM_PART + 768 + tid] + sm[SM_PART + 896 + tid])
                     + sm[SM_MV + 2] * sm[SM_WR + tid];
            sm[SM_BIND + tid] = bv;
        }
        __syncthreads();

        // --- F: bp GEMV ---
        if (tid < 128) {
            int cg = tid & 3, iseg = tid >> 2;
            const uint4* W = (const uint4*)(hs + WS_BP) + cg;
            float a0=0,a1=0,a2=0,a3=0,a4=0,a5=0,a6=0,a7=0;
#pragma unroll
            for (int r = 0; r < 4; r++) {
                int row = iseg + 32 * r;
                float xv = sm[SM_BIND + row];
                uint4 w = W[row * 4];
                FMA8(w, xv);
            }
            float* P = sm + SM_PART + iseg * 32 + cg * 8;
            P[0]=a0; P[1]=a1; P[2]=a2; P[3]=a3; P[4]=a4; P[5]=a5; P[6]=a6; P[7]=a7;
        }
        __syncthreads();
        // --- G: reduce + async exchange ---
        if (tid < 32) {
            float p0 = sm[SM_BPB2 + tid], p1 = 0.f, p2 = 0.f, p3 = 0.f;
#pragma unroll
            for (int sg = 0; sg < 32; sg += 4) {
                p0 += sm[SM_PART + sg * 32 + tid];
                p1 += sm[SM_PART + (sg + 1) * 32 + tid];
                p2 += sm[SM_PART + (sg + 2) * 32 + tid];
                p3 += sm[SM_PART + (sg + 3) * 32 + tid];
            }
            bcast_async(sm + SM_EXCH + set * 256 + rk * 32 + tid, MB + 0 * 4, (p0 + p1) + (p2 + p3));
        }
        mbar_wait(MB + 0 * 4, par);
        // --- H: xh += exch ---
        if (tid < 256) sm[SM_XH + tid] += sm[SM_EXCH + set * 256 + tid];
        __syncthreads();

        // --- DeltaNet layers ---
#pragma unroll
        for (int l = 0; l < 2; l++) {
            // I: qkv GEMV + beta
            if (tid < 384) {
                int cg = tid % 12, iseg = tid / 12;
                const uint4* W = (const uint4*)(hs + WS_QKV) + (size_t)l * 3072 + cg;
                float a0=0,a1=0,a2=0,a3=0,a4=0,a5=0,a6=0,a7=0;
#pragma unroll
                for (int r = 0; r < 8; r++) {
                    int row = iseg + 32 * r;
                    float xv = sm[SM_XH + row];
                    uint4 w = W[row * 12];
                    FMA8(w, xv);
                }
                float* P = sm + SM_PART + iseg * 96 + cg * 8;
                P[0]=a0; P[1]=a1; P[2]=a2; P[3]=a3; P[4]=a4; P[5]=a5; P[6]=a6; P[7]=a7;
            } else {
                int c = (tid - 384) >> 5;
                const __half* Wb = hs + WS_BETA + l * 1024;
                float acc = 0.f;
#pragma unroll
                for (int j = 0; j < 8; j++) {
                    int row = la + 32 * j;
                    acc += sm[SM_XH + row] * __half2float(Wb[row * 4 + c]);
                }
#pragma unroll
                for (int o = 16; o > 0; o >>= 1) acc += __shfl_xor_sync(0xffffffffu, acc, o);
                if (la == 0) {
                    float z = acc + sm[SM_BBETA + l * 4 + c];
                    sm[SM_BETA + c] = 1.f / (1.f + __expf(-z));
                }
            }
            __syncthreads();
            // J: reduce + async exchange qkv
            if (tid < 96) {
                float p0 = sm[SM_BQKV2 + l * 96 + tid], p1 = 0.f, p2 = 0.f, p3 = 0.f;
#pragma unroll
                for (int sg = 0; sg < 32; sg += 4) {
                    p0 += sm[SM_PART + sg * 96 + tid];
                    p1 += sm[SM_PART + (sg + 1) * 96 + tid];
                    p2 += sm[SM_PART + (sg + 2) * 96 + tid];
                    p3 += sm[SM_PART + (sg + 3) * 96 + tid];
                }
                bcast_async(sm + SM_QKV + set * 768 + rk * 96 + tid, MB + (1 + 2 * l) * 4, (p0 + p1) + (p2 + p3));
            }
            mbar_wait(MB + (1 + 2 * l) * 4, par);
            const float* qkvb = sm + SM_QKV + set * 768;

            // M: fused k-norm + state update (owners of layer l)
            if (l_own == l) {
                const float* kr = qkvb + 256 + h_own * 64;
                const float* qh = qkvb + h_own * 64;
                float n0 = 0.f, n1 = 0.f, n2 = 0.f, n3 = 0.f;
                float s0 = 0.f, s1 = 0.f, s2 = 0.f, s3 = 0.f;
#pragma unroll
                for (int j = 0; j < 64; j += 4) {
                    float k0 = kr[j], k1 = kr[j + 1], k2 = kr[j + 2], k3 = kr[j + 3];
                    n0 += k0 * k0; n1 += k1 * k1; n2 += k2 * k2; n3 += k3 * k3;
                    s0 += Sreg[j] * k0;     s1 += Sreg[j + 1] * k1;
                    s2 += Sreg[j + 2] * k2; s3 += Sreg[j + 3] * k3;
                }
                float inv = 1.f / (sqrtf((n0 + n1) + (n2 + n3)) + 1e-6f);
                float sk = ((s0 + s1) + (s2 + s3)) * inv;
                float delta = sm[SM_BETA + h_own] * (qkvb[512 + h_own * 64 + i_own] - sk);
                float d2 = delta * inv;
                float o0 = 0.f, o1 = 0.f, o2 = 0.f, o3 = 0.f;
#pragma unroll
                for (int j = 0; j < 64; j += 4) {
                    Sreg[j]     += d2 * kr[j];     o0 += Sreg[j] * qh[j];
                    Sreg[j + 1] += d2 * kr[j + 1]; o1 += Sreg[j + 1] * qh[j + 1];
                    Sreg[j + 2] += d2 * kr[j + 2]; o2 += Sreg[j + 2] * qh[j + 2];
                    Sreg[j + 3] += d2 * kr[j + 3]; o3 += Sreg[j + 3] * qh[j + 3];
                }
                sm[SM_O + h_own * 64 + i_own] = (o0 + o1) + (o2 + o3);
            }
            __syncthreads();
            // N: wo GEMV
            if (tid < 256) {
                int cg = tid & 3, iseg = tid >> 2;
                const uint4* W = (const uint4*)(hs + WS_WO) + (size_t)l * 1024 + cg;
                float a0=0,a1=0,a2=0,a3=0,a4=0,a5=0,a6=0,a7=0;
#pragma unroll
                for (int r = 0; r < 4; r++) {
                    int row = iseg + 64 * r;
                    float xv = sm[SM_O + row];
                    uint4 w = W[row * 4];
                    FMA8(w, xv);
                }
                float* P = sm + SM_PART + iseg * 32 + cg * 8;
                P[0]=a0; P[1]=a1; P[2]=a2; P[3]=a3; P[4]=a4; P[5]=a5; P[6]=a6; P[7]=a7;
            }
            __syncthreads();
            // O: reduce + async exchange wout + piggybacked LN stats
            if (tid < 32) {
                float p0 = sm[SM_BO2 + l * 32 + tid], p1 = 0.f, p2 = 0.f, p3 = 0.f;
#pragma unroll
                for (int sg = 0; sg < 64; sg += 4) {
                    p0 += sm[SM_PART + sg * 32 + tid];
                    p1 += sm[SM_PART + (sg + 1) * 32 + tid];
                    p2 += sm[SM_PART + (sg + 2) * 32 + tid];
                    p3 += sm[SM_PART + (sg + 3) * 32 + tid];
                }
                float p = (p0 + p1) + (p2 + p3);
                bcast_async(sm + SM_WOUT + set * 256 + rk * 32 + tid, MB + (2 + 2 * l) * 4, p);
                // local LN partials over this rank's 32 columns
                float t = sm[SM_XH + rk * 32 + tid] + p;
                float q1 = t, q2 = t * t;
#pragma unroll
                for (int o = 16; o > 0; o >>= 1) {
                    q1 += __shfl_xor_sync(0xffffffffu, q1, o);
                    q2 += __shfl_xor_sync(0xffffffffu, q2, o);
                }
                if (tid == 0) {
                    bcast_async(sm + SM_STAT + set * 16 + rk * 2,     MB + (2 + 2 * l) * 4, q1);
                    bcast_async(sm + SM_STAT + set * 16 + rk * 2 + 1, MB + (2 + 2 * l) * 4, q2);
                }
            }
            mbar_wait(MB + (2 + 2 * l) * 4, par);
            const float* woutb = sm + SM_WOUT + set * 256;

            // R: normalize (stats summed from rank partials; no separate phase)
            if (tid < 256) {
                const float* st = sm + SM_STAT + set * 16;
                float s1 = ((st[0] + st[2]) + (st[4] + st[6]))
                         + ((st[8] + st[10]) + (st[12] + st[14]));
                float s2 = ((st[1] + st[3]) + (st[5] + st[7]))
                         + ((st[9] + st[11]) + (st[13] + st[15]));
                float m = s1 / 256.f;
                float rsig = rsqrtf(s2 / 256.f - m * m + 1e-5f);
                float r = sm[SM_XH + tid] + woutb[tid];
                sm[SM_XH + tid] = (r - m) * rsig
                                * sm[SM_LNG + l * 256 + tid] + sm[SM_LNB + l * 256 + tid];
            }
            __syncthreads();
        }

        // --- S: sup GEMV + stage q_{s+1} + xh export (rk0) ---
        if (tid < 128) {
            sm[SM_QN + tid] = pf_q;   // next-token q for fused logits in U
            int cg = tid & 1, iseg = tid >> 1;
            const uint4* W = (const uint4*)(hs + WS_SUP) + cg;
            float a0=0,a1=0,a2=0,a3=0,a4=0,a5=0,a6=0,a7=0;
#pragma unroll
            for (int r = 0; r < 4; r++) {
                int row = iseg + 64 * r;
                float xv = sm[SM_XH + row];
                uint4 w = W[row * 2];
                FMA8(w, xv);
            }
            float* P = sm + SM_PART + iseg * 16 + cg * 8;
            P[0]=a0; P[1]=a1; P[2]=a2; P[3]=a3; P[4]=a4; P[5]=a5; P[6]=a6; P[7]=a7;
        } else if (tid >= 256 && rk == 0) {
            g_rx[tok * 384 + 128 + (tid - 256)] = sm[SM_XH + tid - 256];
        }
        __syncthreads();
        // --- T: reduce + async exchange u ---
        if (tid < 16) {
            float p0 = 0.f, p1 = 0.f, p2 = 0.f, p3 = 0.f;
#pragma unroll
            for (int sg = 0; sg < 64; sg += 4) {
                p0 += sm[SM_PART + sg * 16 + tid];
                p1 += sm[SM_PART + (sg + 1) * 16 + tid];
                p2 += sm[SM_PART + (sg + 2) * 16 + tid];
                p3 += sm[SM_PART + (sg + 3) * 16 + tid];
            }
            bcast_async(sm + SM_U + set * 128 + rk * 16 + tid, MB + 5 * 4, (p0 + p1) + (p2 + p3));
        }
        mbar_wait(MB + 5 * 4, par);
        // --- U: fused slot update + next-step attn1 logits ---
        {
            const float* ub = sm + SM_U + set * 128;
            float w0 = sm[SM_WR + la],       w1 = sm[SM_WR + la + 32],
                  w2 = sm[SM_WR + la + 64],  w3 = sm[SM_WR + la + 96];
            float u0 = ub[la],      u1 = ub[la + 32],
                  u2 = ub[la + 64], u3 = ub[la + 96];
            float b0 = sm[SM_SUPB + la],      b1 = sm[SM_SUPB + la + 32],
                  b2 = sm[SM_SUPB + la + 64], b3 = sm[SM_SUPB + la + 96];
            float q0 = sm[SM_QN + la],      q1 = sm[SM_QN + la + 32],
                  q2 = sm[SM_QN + la + 64], q3 = sm[SM_QN + la + 96];
#pragma unroll
            for (int r = 0; r < 4; r++) {
                int n = wp * 4 + r;
                float c1 = sm[SM_C1 + n], c2 = sm[SM_C2 + n];
                float t1 = sm[SM_T1 + n], g2 = sm[SM_G2 + n];
                float* row = sm + SM_SLOTS + n * 128;
                float s0 = c1 * row[la]      + c2 * w0 + t1 * u0 + g2 * b0;
                float s1 = c1 * row[la + 32] + c2 * w1 + t1 * u1 + g2 * b1;
                float s2 = c1 * row[la + 64] + c2 * w2 + t1 * u2 + g2 * b2;
                float s3 = c1 * row[la + 96] + c2 * w3 + t1 * u3 + g2 * b3;
                row[la] = s0; row[la + 32] = s1; row[la + 64] = s2; row[la + 96] = s3;
                float p = s0 * q0 + s1 * q1 + s2 * q2 + s3 * q3;
#pragma unroll
                for (int o = 16; o > 0; o >>= 1) p += __shfl_xor_sync(0xffffffffu, p, o);
                if (la == 0) sm[SM_ABUF + n] = p * invscale;
            }
        }
        __syncthreads();
    }
    cluster_sync_();   // keep cluster resident until all remote stores landed
}

// ---------------------------------------------------------------------------
__global__ __launch_bounds__(512) void k_out(
    const float* __restrict__ sb_wo, const float* __restrict__ sb_bo,
    const float* __restrict__ op_w, const float* __restrict__ op_b,
    const float* __restrict__ oln_g, const float* __restrict__ oln_b,
    const float* __restrict__ ow, const float* __restrict__ ob,
    float* __restrict__ out)
{
    __shared__ float rx[8 * 384];
    __shared__ float yt[8 * 512];
    __shared__ float mv[8][2];
    const int t0 = blockIdx.x * 8;
    const int tid = threadIdx.x;
    const float* src = g_rx + (size_t)t0 * 384;
    for (int idx = tid; idx < 8 * 384; idx += 512) rx[idx] = src[idx];
    __syncthreads();

    {
        float acc[8];
        float bias = sb_bo[tid] + op_b[tid];
#pragma unroll
        for (int t = 0; t < 8; t++) acc[t] = bias;
        const float* w1 = sb_wo + tid;
        for (int i = 0; i < 128; i++) {
            float wv = w1[(size_t)i * 512];
#pragma unroll
            for (int t = 0; t < 8; t++) acc[t] += rx[t * 384 + i] * wv;
        }
        const float* w2 = op_w + tid;
        for (int i = 0; i < 256; i++) {
            float wv = w2[(size_t)i * 512];
#pragma unroll
            for (int t = 0; t < 8; t++) acc[t] += rx[t * 384 + 128 + i] * wv;
        }
#pragma unroll
        for (int t = 0; t < 8; t++) yt[t * 512 + tid] = acc[t];
    }
    __syncthreads();

    if (tid < 256) {
        int tt = tid >> 5, lane = tid & 31;
        float s1 = 0.f, s2 = 0.f;
        for (int i = lane; i < 512; i += 32) { float v = yt[tt * 512 + i]; s1 += v; s2 += v * v; }
#pragma unroll
        for (int o = 16; o > 0; o >>= 1) {
            s1 += __shfl_xor_sync(0xffffffffu, s1, o);
            s2 += __shfl_xor_sync(0xffffffffu, s2, o);
        }
        if (lane == 0) {
            float m = s1 / 512.f;
            mv[tt][0] = m;
            mv[tt][1] = rsqrtf(s2 / 512.f - m * m + 1e-5f);
        }
    }
    __syncthreads();
    for (int idx = tid; idx < 8 * 512; idx += 512) {
        int tt = idx >> 9, c = idx & 511;
        yt[idx] = (yt[idx] - mv[tt][0]) * mv[tt][1] * oln_g[c] + oln_b[c];
    }
    __syncthreads();

    float acc[8];
#pragma unroll
    for (int t = 0; t < 8; t++) acc[t] = ob[tid];
    const float* w = ow + tid;
    for (int i = 0; i < 512; i++) {
        float wv = w[(size_t)i * 512];
#pragma unroll
        for (int t = 0; t < 8; t++) acc[t] += yt[t * 512 + i] * wv;
    }
    float* dst = out + (size_t)t0 * 512;
#pragma unroll
    for (int t = 0; t < 8; t++) dst[t * 512 + tid] = acc[t];
}

// ---------------------------------------------------------------------------
extern "C" void kernel_launch(void* const* d_in, const int* in_sizes, int n_in,
                              void* d_out, int out_size)
{
    const float* x        = (const float*)d_in[0];
    const float* sb_init  = (const float*)d_in[1];
    const float* sb_wq    = (const float*)d_in[2];
    const float* sb_bq    = (const float*)d_in[3];
    const float* sb_ww    = (const float*)d_in[4];
    const float* sb_bw    = (const float*)d_in[5];
    const float* sb_wo    = (const float*)d_in[6];
    const float* sb_bo    = (const float*)d_in[7];
    const float* p_win    = (const float*)d_in[8];
    const float* p_bin    = (const float*)d_in[9];
    const float* b_wq     = (const float*)d_in[10];
    const float* b_bq     = (const float*)d_in[11];
    const float* b_keys   = (const float*)d_in[12];
    const float* bp_w     = (const float*)d_in[13];
    const float* bp_b     = (const float*)d_in[14];
    const float* dn_wqkv  = (const float*)d_in[15];
    const float* dn_bqkv  = (const float*)d_in[16];
    const float* dn_wbeta = (const float*)d_in[17];
    const float* dn_bbeta = (const float*)d_in[18];
    const float* dn_wo    = (const float*)d_in[19];
    const float* dn_bo    = (const float*)d_in[20];
    const float* dn_lng   = (const float*)d_in[21];
    const float* dn_lnb   = (const float*)d_in[22];
    const float* sup_w    = (const float*)d_in[23];
    const float* sup_b    = (const float*)d_in[24];
    const float* op_w     = (const float*)d_in[25];
    const float* op_b     = (const float*)d_in[26];
    const float* oln_g    = (const float*)d_in[27];
    const float* oln_b    = (const float*)d_in[28];
    const float* ow       = (const float*)d_in[29];
    const float* ob       = (const float*)d_in[30];

    static bool attr_set = false;
    if (!attr_set) {
        cudaFuncSetAttribute(k_rec, cudaFuncAttributeMaxDynamicSharedMemorySize, SMEM_REC_BYTES);
        attr_set = true;
    }

    k_cvt<<<(H_TOTAL + 511) / 512, 512>>>(dn_wqkv, dn_wo, bp_w, sup_w, dn_wbeta);
    k_pre<<<512, 512>>>(x, sb_wq, sb_bq, sb_ww, sb_bw, p_win, p_bin);
    k_ba<<<1024, 256>>>(b_wq, b_bq, b_keys);
    k_rec<<<Bv * CLW, 512, SMEM_REC_BYTES>>>(sb_init, bp_b, dn_bqkv, dn_bbeta, dn_bo,
                                             dn_lng, dn_lnb, sup_b);
    k_out<<<1024, 512>>>(sb_wo, sb_bo, op_w, op_b, oln_g, oln_b, ow, ob, (float*)d_out);
}